// round 7
// baseline (speedup 1.0000x reference)
#include <cuda_runtime.h>
#include <math.h>

#define NBLK 128
#define NTHR 256
#define H    256
#define HE   64
#define APER 64
#define NPER 512
#define EPSF 1e-8f
#define INFM 1000000.0f
#define MU_STEP (20.0f/63.0f)
#define INV_SIG (64.0f/20.0f)

// ------------------------- scratch (device globals) --------------------------
__device__ float g_wc [256*320];     // Wq^T @ Wkv[:, :320]
__device__ float g_aux[640];         // [0:256) wqbk, [256:576) biasc, [576] bq.bk
__device__ float g_qke[512*320];
__device__ float g_cb [512*320];     // [n_tilde | s]
__device__ float g_upd[2*512*256];   // split-K partials
__device__ float g_af [512*256];
__device__ float g_m1 [512*512];
__device__ float g_m2 [512*512];
__device__ float g_m3 [2*512*256];   // split-K partials

__device__ unsigned g_bar_count = 0;
__device__ unsigned g_bar_epoch = 0;

// ------------------------- shared structs ------------------------------------
struct GemmSmem { float As[2][16][40]; float Bs[2][16][68]; };
struct AttnSmem {
  float qk[4][H];
  float qek[4][HE];
  float dist[4][NPER];
  float logit[4][NPER];
  float ax[4][3];
  float qbk[4];
  int   list[NPER];
  int   cnt;
  float red[8];
};

// ------------------------- utils ---------------------------------------------
__device__ __forceinline__ float warp_reduce_sum(float v){
#pragma unroll
  for (int o=16;o>0;o>>=1) v += __shfl_xor_sync(0xffffffffu, v, o);
  return v;
}
__device__ __forceinline__ float warp_reduce_max(float v){
#pragma unroll
  for (int o=16;o>0;o>>=1) v = fmaxf(v, __shfl_xor_sync(0xffffffffu, v, o));
  return v;
}

// Software grid barrier. All NBLK blocks are co-resident (NBLK <= SM count),
// so spinning is safe. Epoch is monotonic across graph replays; count returns
// to zero at every barrier, so state is consistent at each launch boundary.
__device__ __forceinline__ void grid_barrier(){
  __syncthreads();
  if (threadIdx.x == 0){
    __threadfence();
    unsigned e = atomicAdd(&g_bar_epoch, 0u);
    unsigned prev = atomicAdd(&g_bar_count, 1u);
    if (prev == gridDim.x - 1){
      atomicExch(&g_bar_count, 0u);
      __threadfence();
      atomicAdd(&g_bar_epoch, 1u);
    } else {
      volatile unsigned* ep = (volatile unsigned*)&g_bar_epoch;
      while (*ep == e) { }
      __threadfence();
    }
  }
  __syncthreads();
}

// ------------------------- GEMM tile (TM x 64), 256 threads ------------------
// A_KM: A is K-major (A[k*lda+m]); else row-major (A[m*lda+k]).
// B_KN: B is (K,N) row-major; else (N,K) row-major (i.e. @ W.T).
template<int TM, bool A_KM, bool B_KN, bool BIAS, bool RELU>
__device__ void gemm_tile(const float* __restrict__ A, int lda,
                          const float* __restrict__ B, int ldb,
                          const float* __restrict__ bias,
                          float* __restrict__ C, int ldc,
                          int m0, int n0, int kbeg, int kend,
                          GemmSmem* sm)
{
  constexpr int RM = TM/16;
  const int tid = threadIdx.x;
  const int tx = tid & 15, ty = tid >> 4;

  // A-chunk load indices
  bool a_act; int a_i0, a_i1;
  if (A_KM){ constexpr int AM4 = TM/4;
    a_act = (tid < 16*AM4); a_i0 = tid / AM4; a_i1 = tid % AM4;      // k-row, m-grp
  } else {
    a_act = (tid < TM*4);   a_i0 = tid >> 2;  a_i1 = tid & 3;        // m-row, k-grp
  }
  // B-chunk load indices (16 x 64 = 256 float4, one per thread)
  int b_i0, b_i1;
  if (B_KN){ b_i0 = tid >> 4; b_i1 = tid & 15; }   // k-row, n-grp
  else     { b_i0 = tid >> 2; b_i1 = tid & 3;  }   // n-row, k-grp

  auto loadA = [&](int k0)->float4 {
    if (!a_act) return make_float4(0.f,0.f,0.f,0.f);
    if (A_KM) return *(const float4*)(A + (size_t)(k0 + a_i0)*lda + m0 + a_i1*4);
    else      return *(const float4*)(A + (size_t)(m0 + a_i0)*lda + k0 + a_i1*4);
  };
  auto loadB = [&](int k0)->float4 {
    if (B_KN) return *(const float4*)(B + (size_t)(k0 + b_i0)*ldb + n0 + b_i1*4);
    else      return *(const float4*)(B + (size_t)(n0 + b_i0)*ldb + k0 + b_i1*4);
  };
  auto storeA = [&](int buf, float4 v){
    if (!a_act) return;
    if (A_KM) *(float4*)&sm->As[buf][a_i0][a_i1*4] = v;
    else {
      sm->As[buf][a_i1*4+0][a_i0] = v.x;
      sm->As[buf][a_i1*4+1][a_i0] = v.y;
      sm->As[buf][a_i1*4+2][a_i0] = v.z;
      sm->As[buf][a_i1*4+3][a_i0] = v.w;
    }
  };
  auto storeB = [&](int buf, float4 v){
    if (B_KN) *(float4*)&sm->Bs[buf][b_i0][b_i1*4] = v;
    else {
      sm->Bs[buf][b_i1*4+0][b_i0] = v.x;
      sm->Bs[buf][b_i1*4+1][b_i0] = v.y;
      sm->Bs[buf][b_i1*4+2][b_i0] = v.z;
      sm->Bs[buf][b_i1*4+3][b_i0] = v.w;
    }
  };

  float acc[RM][4];
#pragma unroll
  for (int i=0;i<RM;i++)
#pragma unroll
    for (int j=0;j<4;j++) acc[i][j] = 0.f;

  __syncthreads();                       // protect smem from prior use
  storeA(0, loadA(kbeg));
  storeB(0, loadB(kbeg));
  __syncthreads();

  int buf = 0;
  for (int k0 = kbeg + 16; ; k0 += 16, buf ^= 1){
    const bool more = (k0 < kend);
    float4 pa, pb;
    if (more){ pa = loadA(k0); pb = loadB(k0); }
#pragma unroll
    for (int kk = 0; kk < 16; kk++){
      float4 bv = *(const float4*)&sm->Bs[buf][kk][tx*4];
#pragma unroll
      for (int i=0;i<RM;i++){
        float a = sm->As[buf][kk][ty*RM + i];
        acc[i][0] = fmaf(a, bv.x, acc[i][0]);
        acc[i][1] = fmaf(a, bv.y, acc[i][1]);
        acc[i][2] = fmaf(a, bv.z, acc[i][2]);
        acc[i][3] = fmaf(a, bv.w, acc[i][3]);
      }
    }
    if (!more) break;
    storeA(buf^1, pa);
    storeB(buf^1, pb);
    __syncthreads();
  }

#pragma unroll
  for (int i=0;i<RM;i++){
    const int m = m0 + ty*RM + i;
    float4 v = make_float4(acc[i][0], acc[i][1], acc[i][2], acc[i][3]);
    if (BIAS){
      float4 bb = *(const float4*)(bias + n0 + tx*4);
      v.x += bb.x; v.y += bb.y; v.z += bb.z; v.w += bb.w;
    }
    if (RELU){
      v.x = fmaxf(v.x,0.f); v.y = fmaxf(v.y,0.f);
      v.z = fmaxf(v.z,0.f); v.w = fmaxf(v.w,0.f);
    }
    *(float4*)(C + (size_t)m*ldc + n0 + tx*4) = v;
  }
}

// ------------------------- residual + LayerNorm (4 rows/block) ---------------
__device__ void ln4(const float* __restrict__ r,
                    const float* __restrict__ p0,
                    const float* __restrict__ p1,      // nullable
                    const float* __restrict__ bias,    // nullable
                    const float* __restrict__ g,
                    const float* __restrict__ b,
                    float* __restrict__ o)
{
  const int warp = threadIdx.x >> 5, lane = threadIdx.x & 31;
  if (warp >= 4) return;
  const size_t row = (size_t)blockIdx.x*4 + warp;
  float v[8]; float s = 0.f;
#pragma unroll
  for (int i=0;i<8;i++){
    int c = lane + i*32;
    float x = r[row*H+c] + p0[row*H+c];
    if (p1)   x += p1[row*H+c];
    if (bias) x += bias[c];
    v[i] = x; s += x;
  }
  s = warp_reduce_sum(s);
  float mean = s * (1.f/H);
  float s2 = 0.f;
#pragma unroll
  for (int i=0;i<8;i++){ float d = v[i]-mean; s2 += d*d; }
  s2 = warp_reduce_sum(s2);
  float inv = rsqrtf(s2*(1.f/H) + 1e-5f);
#pragma unroll
  for (int i=0;i<8;i++){
    int c = lane + i*32;
    o[row*H+c] = (v[i]-mean)*inv*g[c] + b[c];
  }
}

// ------------------------- megakernel ----------------------------------------
__global__ __launch_bounds__(NTHR)
void mega(const float* __restrict__ anchor_x,
          const float* __restrict__ node_x,
          const float* __restrict__ afeat,
          const float* __restrict__ nf,
          const float* __restrict__ nmask,
          const float* __restrict__ Wq,  const float* __restrict__ bq,
          const float* __restrict__ Wkv, const float* __restrict__ bkv,
          const float* __restrict__ ln1g, const float* __restrict__ ln1b,
          const float* __restrict__ W1, const float* __restrict__ b1,
          const float* __restrict__ W2, const float* __restrict__ b2,
          const float* __restrict__ W3, const float* __restrict__ b3,
          const float* __restrict__ ln2g, const float* __restrict__ ln2b,
          float* __restrict__ out)
{
  __shared__ GemmSmem sg;
  __shared__ AttnSmem sa;
  const int tid = threadIdx.x, bid = blockIdx.x;
  const int lane = tid & 31, warp = tid >> 5;

  // ========== stage A: wc = Wq^T @ Wkv[:, :320]  +  aux vectors ==============
  if (bid < 80){                                  // 16x5 tiles of 16x64
    int my = bid / 5, nx = bid % 5;
    gemm_tile<16,true,true,false,false>(Wq,256, Wkv,320, nullptr,
        g_wc,320, my*16, nx*64, 0,256, &sg);
  } else if (bid == 80){
    for (int i = tid; i < 256; i += NTHR){
      float s = 0.f;
      for (int j = 0; j < 256; j++) s = fmaf(Wq[(size_t)j*256 + i], bkv[j], s);
      g_aux[i] = s;                               // wqbk
    }
  } else if (bid == 81){
    for (int c = tid; c < 320; c += NTHR){
      float s = 0.f;
      for (int j = 0; j < 256; j++) s = fmaf(bq[j], Wkv[(size_t)j*320 + c], s);
      g_aux[256 + c] = s;                         // biasc
    }
  } else if (bid == 82){
    if (tid == 0){
      float s = 0.f;
      for (int j = 0; j < 256; j++) s = fmaf(bq[j], bkv[j], s);
      g_aux[576] = s;                             // bq.bk
    }
  }
  grid_barrier();

  // ========== stage B: attn prep (smem) + qke GEMM ===========================
  const int a0 = bid*4;
  const int nbase = (a0 / APER) * NPER;

  if (tid == 0) sa.cnt = 0;
  if (tid < 12) sa.ax[tid/3][tid%3] = anchor_x[(size_t)(a0 + tid/3)*3 + (tid%3)];
  __syncthreads();
#pragma unroll
  for (int rep = 0; rep < 2; rep++){
    const int n = tid + rep*256, ng = nbase + n;
    const float x0 = node_x[(size_t)3*ng+0];
    const float x1 = node_x[(size_t)3*ng+1];
    const float x2 = node_x[(size_t)3*ng+2];
#pragma unroll
    for (int a=0;a<4;a++){
      float dx = sa.ax[a][0]-x0+EPSF;
      float dy = sa.ax[a][1]-x1+EPSF;
      float dz = sa.ax[a][2]-x2+EPSF;
      sa.dist[a][n] = sqrtf(dx*dx + dy*dy + dz*dz);
      sa.logit[a][n] = 0.f;
    }
    if (nmask[ng] == 0.0f){
      int p = atomicAdd(&sa.cnt, 1);
      sa.list[p] = n;
    }
  }
  if (warp < 4){                                  // qbk[a] = af.wqbk + bq.bk
    const float* ar = afeat + (size_t)(a0 + warp)*H;
    float s = 0.f;
#pragma unroll
    for (int kk=0;kk<8;kk++) s = fmaf(ar[lane+kk*32], g_aux[lane+kk*32], s);
    s = warp_reduce_sum(s);
    if (lane == 0) sa.qbk[warp] = s + g_aux[576];
  }
  __syncthreads();

  if (bid < 80){                                  // qke: 16x5 tiles of 32x64
    int my = bid / 5, nx = bid % 5;
    gemm_tile<32,false,true,true,false>(afeat,256, g_wc,320, g_aux+256,
        g_qke,320, my*32, nx*64, 0,256, &sg);
  }
  grid_barrier();

  // ========== stage C: attention ============================================
  for (int i = tid; i < 4*320; i += NTHR){
    int r = i / 320, c = i - r*320;
    float v = g_qke[(size_t)(a0 + r)*320 + c];
    if (c < 256) sa.qk[r][c] = v; else sa.qek[r][c-256] = v;
  }
  __syncthreads();

  {                                               // masked logits, warp/node
    const int cnt = sa.cnt;
    const float mu0 = (float)lane * MU_STEP;
    const float mu1 = (float)(lane+32) * MU_STEP;
    for (int i = warp; i < cnt; i += 8){
      const int n = sa.list[i], ng = nbase + n;
      const float4* nf4 = (const float4*)(nf + (size_t)ng*H);
      float4 u0 = nf4[lane], u1 = nf4[lane+32];
#pragma unroll
      for (int a=0;a<4;a++){
        float t = sa.dist[a][n] * 0.1f;
        float z0 = (t - mu0)*INV_SIG, z1 = (t - mu1)*INV_SIG;
        float z0s = z0*z0, z1s = z1*z1;
        float acc = 0.f;
        if (z0s < 64.f) acc  = __expf(-z0s) * sa.qek[a][lane];
        if (z1s < 64.f) acc += __expf(-z1s) * sa.qek[a][lane+32];
        const float4* qa = (const float4*)sa.qk[a];
        float4 q0 = qa[lane], q1 = qa[lane+32];
        acc = fmaf(u0.x,q0.x, fmaf(u0.y,q0.y, fmaf(u0.z,q0.z, fmaf(u0.w,q0.w, acc))));
        acc = fmaf(u1.x,q1.x, fmaf(u1.y,q1.y, fmaf(u1.z,q1.z, fmaf(u1.w,q1.w, acc))));
        acc = warp_reduce_sum(acc);
        if (lane == 0) sa.logit[a][n] = (acc + sa.qbk[a]) * (-INFM);
      }
    }
  }
  __syncthreads();

#pragma unroll
  for (int a=0;a<4;a++){                          // softmax over 512
    float l0 = sa.logit[a][tid], l1 = sa.logit[a][tid+256];
    float m = warp_reduce_max(fmaxf(l0, l1));
    if (lane == 0) sa.red[warp] = m;
    __syncthreads();
    float mx = sa.red[0];
#pragma unroll
    for (int k=1;k<8;k++) mx = fmaxf(mx, sa.red[k]);
    float e0 = __expf(l0 - mx), e1 = __expf(l1 - mx);
    float s = warp_reduce_sum(e0 + e1);
    __syncthreads();
    if (lane == 0) sa.red[warp] = s;
    __syncthreads();
    float sm = 0.f;
#pragma unroll
    for (int k=0;k<8;k++) sm += sa.red[k];
    float inv = 1.f / sm;
    sa.logit[a][tid]     = e0 * inv;
    sa.logit[a][tid+256] = e1 * inv;
    __syncthreads();
  }

  {                                               // C1: s[a][j] = sum attn*rbf
    const int a = tid >> 6, j = tid & 63;
    const float mu = (float)j * MU_STEP;
    float acc = 0.f;
#pragma unroll 4
    for (int n=0;n<NPER;n++){
      float z = (sa.dist[a][n]*0.1f - mu) * INV_SIG;
      float z2 = z*z;
      if (z2 < 60.f) acc = fmaf(sa.logit[a][n], __expf(-z2), acc);
    }
    g_cb[(size_t)(a0+a)*320 + 256 + j] = acc;
  }
  __syncthreads();

  {                                               // C2: n_tilde = attn @ nf
    const int gg = tid >> 7, r = tid & 127;
    float ax0=0.f, ay0=0.f, ax1=0.f, ay1=0.f, ax2=0.f, ay2=0.f, ax3=0.f, ay3=0.f;
    const float* base = nf + (size_t)(nbase + gg*256)*H + 2*r;
    const int nb0 = gg*256;
    for (int nn=0;nn<256;nn++){
      float2 f = *(const float2*)(base + (size_t)nn*H);
      float w0 = sa.logit[0][nb0+nn];
      float w1 = sa.logit[1][nb0+nn];
      float w2 = sa.logit[2][nb0+nn];
      float w3 = sa.logit[3][nb0+nn];
      ax0 = fmaf(w0, f.x, ax0); ay0 = fmaf(w0, f.y, ay0);
      ax1 = fmaf(w1, f.x, ax1); ay1 = fmaf(w1, f.y, ay1);
      ax2 = fmaf(w2, f.x, ax2); ay2 = fmaf(w2, f.y, ay2);
      ax3 = fmaf(w3, f.x, ax3); ay3 = fmaf(w3, f.y, ay3);
    }
    __syncthreads();
    if (gg == 1){
      sa.dist[0][2*r] = ax0; sa.dist[0][2*r+1] = ay0;
      sa.dist[1][2*r] = ax1; sa.dist[1][2*r+1] = ay1;
      sa.dist[2][2*r] = ax2; sa.dist[2][2*r+1] = ay2;
      sa.dist[3][2*r] = ax3; sa.dist[3][2*r+1] = ay3;
    }
    __syncthreads();
    if (gg == 0){
      g_cb[(size_t)(a0+0)*320 + 2*r]   = ax0 + sa.dist[0][2*r];
      g_cb[(size_t)(a0+0)*320 + 2*r+1] = ay0 + sa.dist[0][2*r+1];
      g_cb[(size_t)(a0+1)*320 + 2*r]   = ax1 + sa.dist[1][2*r];
      g_cb[(size_t)(a0+1)*320 + 2*r+1] = ay1 + sa.dist[1][2*r+1];
      g_cb[(size_t)(a0+2)*320 + 2*r]   = ax2 + sa.dist[2][2*r];
      g_cb[(size_t)(a0+2)*320 + 2*r+1] = ay2 + sa.dist[2][2*r+1];
      g_cb[(size_t)(a0+3)*320 + 2*r]   = ax3 + sa.dist[3][2*r];
      g_cb[(size_t)(a0+3)*320 + 2*r+1] = ay3 + sa.dist[3][2*r+1];
    }
  }
  grid_barrier();

  // ========== stage D: upd partials (split-K=2) ==============================
  {
    const int z = bid >> 6, tt = bid & 63;        // 2 x (16x4) instances
    const int my = tt >> 2, nx = tt & 3;
    gemm_tile<32,false,false,false,false>(g_cb,320, Wkv + (size_t)256*320,320,
        nullptr, g_upd + (size_t)z*512*256, 256,
        my*32, nx*64, z*160, z*160 + 160, &sg);
  }
  grid_barrier();

  // ========== stage E: af = LN1(afeat + upd0 + upd1 + bkv_v) =================
  ln4(afeat, g_upd, g_upd + (size_t)512*256, bkv + 256, ln1g, ln1b, g_af);
  grid_barrier();

  // ========== stage F: m1 = relu(af @ W1.T + b1) =============================
  {
    const int my = bid >> 3, nx = bid & 7;        // 16x8 tiles
    gemm_tile<32,false,false,true,true>(g_af,256, W1,256, b1,
        g_m1,512, my*32, nx*64, 0,256, &sg);
  }
  grid_barrier();

  // ========== stage G: m2 = relu(m1 @ W2.T + b2) =============================
  {
    const int my = bid >> 3, nx = bid & 7;        // 16x8 tiles
    gemm_tile<32,false,false,true,true>(g_m1,512, W2,512, b2,
        g_m2,512, my*32, nx*64, 0,512, &sg);
  }
  grid_barrier();

  // ========== stage H: m3 partials (split-K=2) ===============================
  {
    const int z = bid >> 6, tt = bid & 63;        // 2 x (16x4) instances
    const int my = tt >> 2, nx = tt & 3;
    gemm_tile<32,false,false,false,false>(g_m2,512, W3,512, nullptr,
        g_m3 + (size_t)z*512*256, 256,
        my*32, nx*64, z*256, z*256 + 256, &sg);
  }
  grid_barrier();

  // ========== stage I: out = LN2(af + m3a + m3b + b3) ========================
  ln4(g_af, g_m3, g_m3 + (size_t)512*256, b3, ln2g, ln2b, out);
}

// ------------------------- launch ---------------------------------------------
extern "C" void kernel_launch(void* const* d_in, const int* in_sizes, int n_in,
                              void* d_out, int out_size)
{
  const float* anchor_x        = (const float*)d_in[0];
  const float* node_x          = (const float*)d_in[1];
  const float* anchor_features = (const float*)d_in[2];
  const float* node_features   = (const float*)d_in[3];
  const float* node_mask       = (const float*)d_in[6];
  const float* Wq              = (const float*)d_in[7];
  const float* bq              = (const float*)d_in[8];
  const float* Wkv             = (const float*)d_in[9];
  const float* bkv             = (const float*)d_in[10];
  const float* ln1_g           = (const float*)d_in[11];
  const float* ln1_b           = (const float*)d_in[12];
  const float* W1              = (const float*)d_in[13];
  const float* b1              = (const float*)d_in[14];
  const float* W2              = (const float*)d_in[15];
  const float* b2              = (const float*)d_in[16];
  const float* W3              = (const float*)d_in[17];
  const float* b3              = (const float*)d_in[18];
  const float* ln2_g           = (const float*)d_in[19];
  const float* ln2_b           = (const float*)d_in[20];
  float* out = (float*)d_out;

  mega<<<NBLK, NTHR>>>(anchor_x, node_x, anchor_features, node_features,
                       node_mask, Wq, bq, Wkv, bkv, ln1_g, ln1_b,
                       W1, b1, W2, b2, W3, b3, ln2_g, ln2_b, out);
}